// round 12
// baseline (speedup 1.0000x reference)
#include <cuda_runtime.h>
#include <cuda_bf16.h>
#include <math.h>
#include <stdint.h>

// ---------------- problem constants ----------------
static constexpr int NTOK = 2048;
static constexpr int Dm   = 1024;
static constexpr int NEXP = 12;
static constexpr int HSh  = 2048;   // shared hidden
static constexpr int HRt  = 3072;   // routed hidden
static constexpr float TAU = 1.5f;
static constexpr int NGRP = 3, EPG = NEXP / NGRP;   // expert pipeline groups

// ---------------- device scratch ----------------
__device__ int   g_cnt[NEXP];
__device__ int   g_off[NEXP];
__device__ int   g_bucket[NEXP * NTOK];
__device__ float g_bw[NEXP * NTOK];

__device__ __nv_bfloat16 g_xh[(size_t)NTOK * Dm],  g_xl[(size_t)NTOK * Dm];
__device__ __nv_bfloat16 g_ash[(size_t)NTOK * HSh], g_asl[(size_t)NTOK * HSh];
__device__ __nv_bfloat16 g_arh[(size_t)2 * NTOK * HRt], g_arl[(size_t)2 * NTOK * HRt];
// converted weights, SAME [K, N] layout as source (W1: a/g column-interleaved)
__device__ __nv_bfloat16 g_w1h[(size_t)Dm * 2 * HSh], g_w1l[(size_t)Dm * 2 * HSh];
__device__ __nv_bfloat16 g_w2h[(size_t)HSh * Dm],     g_w2l[(size_t)HSh * Dm];
__device__ __nv_bfloat16 g_e1h[(size_t)NEXP * Dm * 2 * HRt], g_e1l[(size_t)NEXP * Dm * 2 * HRt];
__device__ __nv_bfloat16 g_e2h[(size_t)NEXP * HRt * Dm],     g_e2l[(size_t)NEXP * HRt * Dm];

// ---------------- helpers ----------------
__device__ __forceinline__ uint32_t smem_u32(const void* p) {
    uint32_t a;
    asm("{ .reg .u64 t; cvta.to.shared.u64 t, %1; cvt.u32.u64 %0, t; }" : "=r"(a) : "l"(p));
    return a;
}
__device__ __forceinline__ uint32_t swzA(uint32_t b) { return b ^ ((b >> 3) & 0x70); }
// B tile: [64 k-rows][64 n-cols bf16] = 128B rows; 16B-granule xor swizzle
__device__ __forceinline__ uint32_t bofs(int k, int nb) {
    return (uint32_t)(k * 128 + (((nb >> 4) ^ (k & 7)) << 4) + (nb & 15));
}

__device__ __forceinline__ void cp16(uint32_t dst, const void* src, int sz) {
    asm volatile("cp.async.cg.shared.global [%0], [%1], 16, %2;"
                 :: "r"(dst), "l"(src), "r"(sz));
}
#define CP_COMMIT() asm volatile("cp.async.commit_group;" ::: "memory")

__device__ __forceinline__ void ldsm4(uint32_t* r, uint32_t addr) {
    asm volatile("ldmatrix.sync.aligned.m8n8.x4.shared.b16 {%0,%1,%2,%3}, [%4];"
                 : "=r"(r[0]), "=r"(r[1]), "=r"(r[2]), "=r"(r[3]) : "r"(addr));
}
__device__ __forceinline__ void ldsm4t(uint32_t* r, uint32_t addr) {
    asm volatile("ldmatrix.sync.aligned.m8n8.x4.trans.shared.b16 {%0,%1,%2,%3}, [%4];"
                 : "=r"(r[0]), "=r"(r[1]), "=r"(r[2]), "=r"(r[3]) : "r"(addr));
}
__device__ __forceinline__ void mma16816(float* c, const uint32_t* a, const uint32_t* b) {
    asm volatile(
        "mma.sync.aligned.m16n8k16.row.col.f32.bf16.bf16.f32 "
        "{%0,%1,%2,%3}, {%4,%5,%6,%7}, {%8,%9}, {%0,%1,%2,%3};"
        : "+f"(c[0]), "+f"(c[1]), "+f"(c[2]), "+f"(c[3])
        : "r"(a[0]), "r"(a[1]), "r"(a[2]), "r"(a[3]), "r"(b[0]), "r"(b[1]));
}
__device__ __forceinline__ void split_bf16(float v, __nv_bfloat16& h, __nv_bfloat16& l) {
    h = __float2bfloat16(v);
    l = __float2bfloat16(v - __bfloat162float(h));
}
__device__ __forceinline__ uint32_t pack2(__nv_bfloat16 a, __nv_bfloat16 b) {
    return (uint32_t)__bfloat16_as_ushort(a) | ((uint32_t)__bfloat16_as_ushort(b) << 16);
}
__device__ __forceinline__ float gelu_exact(float g) {
    return 0.5f * g * (1.0f + erff(g * 0.70710678118654752f));
}

// ---------------- tiny kernels ----------------
__global__ void zero_k() { if (threadIdx.x < NEXP) g_cnt[threadIdx.x] = 0; }

__global__ void prefix_k() {
    if (threadIdx.x == 0) {
        int s = 0;
        for (int e = 0; e < NEXP; e++) { g_off[e] = s; s += g_cnt[e]; }
    }
}

__global__ void router_k(const float* __restrict__ x,
                         const float* __restrict__ Wr,
                         const float* __restrict__ br) {
    int n = blockIdx.x, tid = threadIdx.x;            // 128 threads
    __shared__ float red[128 * NEXP];
    __shared__ float lg[NEXP];
    float part[NEXP];
#pragma unroll
    for (int e = 0; e < NEXP; e++) part[e] = 0.f;
    const float* xr = x + (size_t)n * Dm;
    for (int d = tid; d < Dm; d += 128) {
        float xv = xr[d];
        const float* wr = Wr + (size_t)d * NEXP;
#pragma unroll
        for (int e = 0; e < NEXP; e++) part[e] += xv * wr[e];
    }
#pragma unroll
    for (int e = 0; e < NEXP; e++) red[tid * NEXP + e] = part[e];
    __syncthreads();
    if (tid < NEXP) {
        float s = 0.f;
        for (int i = 0; i < 128; i++) s += red[i * NEXP + tid];
        lg[tid] = (s + br[tid]) / TAU;
    }
    __syncthreads();
    if (tid == 0) {
        int i0 = 0; float v0 = lg[0];
#pragma unroll
        for (int e = 1; e < NEXP; e++) if (lg[e] > v0) { v0 = lg[e]; i0 = e; }
        int i1 = -1; float v1 = -3.4e38f;
#pragma unroll
        for (int e = 0; e < NEXP; e++) if (e != i0 && lg[e] > v1) { v1 = lg[e]; i1 = e; }
        float e1 = __expf(v1 - v0);
        float inv = 1.f / (1.f + e1);
        int s0 = atomicAdd(&g_cnt[i0], 1);
        g_bucket[i0 * NTOK + s0] = n;  g_bw[i0 * NTOK + s0] = inv;
        int s1 = atomicAdd(&g_cnt[i1], 1);
        g_bucket[i1 * NTOK + s1] = n;  g_bw[i1 * NTOK + s1] = e1 * inv;
    }
}

// vectorized split fp32 -> bf16 hi/lo (layout-preserving, n multiple of 4)
__global__ void split_k(const float4* __restrict__ s, uint2* __restrict__ dh,
                        uint2* __restrict__ dl, int n4) {
    int i = blockIdx.x * 256 + threadIdx.x;
    if (i >= n4) return;
    float4 v = s[i];
    __nv_bfloat16 h[4], l[4];
    split_bf16(v.x, h[0], l[0]); split_bf16(v.y, h[1], l[1]);
    split_bf16(v.z, h[2], l[2]); split_bf16(v.w, h[3], l[3]);
    dh[i] = make_uint2(pack2(h[0], h[1]), pack2(h[2], h[3]));
    dl[i] = make_uint2(pack2(l[0], l[1]), pack2(l[2], l[3]));
}

// W1 conversion: fp32 [K, 2H] -> bf16 hi/lo [K, 2H] with a/g column interleave
__global__ void wsplit_ilv_k(const float* __restrict__ W, __nv_bfloat16* __restrict__ oh,
                             __nv_bfloat16* __restrict__ ol, int K, int H) {
    int i = blockIdx.x * 256 + threadIdx.x;
    if (i >= K * H) return;
    int k = i / H, c = i - k * H;
    size_t zo = (size_t)blockIdx.y * K * 2 * H;
    const float* wr = W + zo + (size_t)k * 2 * H;
    float a = wr[c], g = wr[H + c];
    __nv_bfloat16 ah, al, gh, gl;
    split_bf16(a, ah, al); split_bf16(g, gh, gl);
    size_t o = zo + (size_t)k * 2 * H + 2 * c;
    *(uint32_t*)(oh + o) = pack2(ah, gh);
    *(uint32_t*)(ol + o) = pack2(al, gl);
}

// ---------------- HMMA bf16x3 GEMM ----------------
// CTA 128M x 64N, 256 thr, 8 warps (4M x 2N), warp tile 32x32, 2 CTAs/SM.
// A: bf16 hi/lo [M,K] (swzA, ldsm4). B: bf16 hi/lo [K,N] (bofs, ldsm4t).
// MODE 0 plain store; MODE 1 A via bucket (expert=ebase+blockIdx.z), out row off[e]+m;
// MODE 2 A rows off[e]+m, atomicAdd(C[token], w*(acc+bias));
// MODE 3 plain rows, atomicAdd(C[row], acc+bias)   (shared GEMM2 accumulate).
static constexpr int AT_B  = 16384;                 // A tile 128x64x2B
static constexpr int BT_B  = 8192;                  // B tile 64x64x2B
static constexpr int STG_B = 2 * AT_B + 2 * BT_B;   // 49152
static constexpr int GSMEM = 2 * STG_B;             // 98304

template <int MODE, bool GEGLU>
__global__ void __launch_bounds__(256, 2)
fgemm(const __nv_bfloat16* __restrict__ Ah, const __nv_bfloat16* __restrict__ Al,
      const __nv_bfloat16* __restrict__ Bh, const __nv_bfloat16* __restrict__ Bl,
      const float* __restrict__ bias, float* __restrict__ C,
      __nv_bfloat16* __restrict__ OH, __nv_bfloat16* __restrict__ OL,
      int M, int N, int K, int ebase) {
    extern __shared__ char sm[];
    __shared__ int   sb_tok[128];
    __shared__ float sb_w[128];

    constexpr bool ROUTED = (MODE == 1 || MODE == 2);
    const int tid = threadIdx.x, wid = tid >> 5, lane = tid & 31;
    const int wm = wid & 3, wn = wid >> 2;
    const int row0 = blockIdx.y * 128, col0 = blockIdx.x * 64;

    int e = 0, Me = M, offE = 0;
    if constexpr (ROUTED) {
        e = ebase + blockIdx.z;
        Me = g_cnt[e];
        if (row0 >= Me) return;
        offE = g_off[e];
        Bh += (size_t)e * K * N;
        Bl += (size_t)e * K * N;
        bias += (size_t)e * N;
        if (tid < 128) {
            int r = row0 + tid;
            sb_tok[tid] = (r < Me) ? g_bucket[e * NTOK + r] : 0;
            sb_w[tid]   = (r < Me) ? g_bw[e * NTOK + r] : 0.f;
        }
        __syncthreads();
    }

    const int nch = K >> 6;
    const uint32_t smb = smem_u32(sm);

    auto issue_chunk = [&](int ck) {
        const int k0 = ck << 6;
        const uint32_t base = smb + (ck & 1) * STG_B;
#pragma unroll
        for (int s = tid; s < 2048; s += 256) {
            int t = s >> 10, slot = s & 1023;
            int r = slot >> 3, cc = slot & 7;
            uint32_t dst = base + t * AT_B + swzA((uint32_t)(r * 128 + cc * 16));
            const __nv_bfloat16* Ab = (t == 0) ? Ah : Al;
            size_t ro = 0; int sz = 16;
            if constexpr (MODE == 1) {
                if (row0 + r < Me) ro = (size_t)sb_tok[r] * K; else sz = 0;
            } else if constexpr (MODE == 2) {
                if (row0 + r < Me) ro = (size_t)(offE + row0 + r) * K; else sz = 0;
            } else {
                ro = (size_t)(row0 + r) * K;
            }
            cp16(dst, Ab + ro + k0 + cc * 8, sz);
        }
#pragma unroll
        for (int s = tid; s < 1024; s += 256) {
            int t = s >> 9, slot = s & 511;
            int k = slot >> 3, j16 = slot & 7;
            uint32_t dst = base + 2 * AT_B + t * BT_B + bofs(k, j16 * 16);
            const __nv_bfloat16* Bb = (t == 0) ? Bh : Bl;
            cp16(dst, Bb + (size_t)(k0 + k) * N + col0 + j16 * 8, 16);
        }
        CP_COMMIT();
    };

    float acc[2][4][4];
#pragma unroll
    for (int i = 0; i < 2; i++)
#pragma unroll
        for (int j = 0; j < 4; j++)
#pragma unroll
            for (int k = 0; k < 4; k++) acc[i][j][k] = 0.f;

    issue_chunk(0);
    for (int ck = 0; ck < nch; ck++) {
        if (ck + 1 < nch) {
            issue_chunk(ck + 1);
            asm volatile("cp.async.wait_group 1;" ::: "memory");
        } else {
            asm volatile("cp.async.wait_group 0;" ::: "memory");
        }
        __syncthreads();

        const uint32_t base = smb + (ck & 1) * STG_B;
        const uint32_t tAh = base, tAl = base + AT_B;
        const uint32_t tBh = base + 2 * AT_B, tBl = tBh + BT_B;

#pragma unroll
        for (int ks = 0; ks < 4; ks++) {
            uint32_t ahf[2][4], alf[2][4];
#pragma unroll
            for (int mt = 0; mt < 2; mt++) {
                int rrow = wm * 32 + mt * 16 + (lane & 15);
                uint32_t byte = swzA((uint32_t)(rrow * 128 + ks * 32 + (lane >> 4) * 16));
                ldsm4(ahf[mt], tAh + byte);
                ldsm4(alf[mt], tAl + byte);
            }
            const int sub = lane >> 3, i8 = lane & 7;
            const int kk = ks * 16 + (sub & 1) * 8 + i8;
            uint32_t bhf[4][2], blf[4][2];
#pragma unroll
            for (int g = 0; g < 2; g++) {
                int nn = wn * 32 + g * 16 + (sub >> 1) * 8;
                uint32_t byte = bofs(kk, nn * 2);
                uint32_t r4[4];
                ldsm4t(r4, tBh + byte);
                bhf[2 * g][0] = r4[0]; bhf[2 * g][1] = r4[1];
                bhf[2 * g + 1][0] = r4[2]; bhf[2 * g + 1][1] = r4[3];
                ldsm4t(r4, tBl + byte);
                blf[2 * g][0] = r4[0]; blf[2 * g][1] = r4[1];
                blf[2 * g + 1][0] = r4[2]; blf[2 * g + 1][1] = r4[3];
            }
#pragma unroll
            for (int mt = 0; mt < 2; mt++)
#pragma unroll
                for (int nf = 0; nf < 4; nf++) {
                    mma16816(acc[mt][nf], ahf[mt], bhf[nf]);
                    mma16816(acc[mt][nf], ahf[mt], blf[nf]);
                    mma16816(acc[mt][nf], alf[mt], bhf[nf]);
                }
        }
        __syncthreads();
    }

    // ---------------- epilogue ----------------
    const int Hout = N >> 1;
#pragma unroll
    for (int mt = 0; mt < 2; mt++) {
#pragma unroll
        for (int half = 0; half < 2; half++) {
            int ml = wm * 32 + mt * 16 + (lane >> 2) + half * 8;
            if constexpr (ROUTED) { if (row0 + ml >= Me) continue; }
#pragma unroll
            for (int nf = 0; nf < 4; nf++) {
                int colb = col0 + wn * 32 + nf * 8 + (lane & 3) * 2;
                if constexpr (GEGLU) {
                    int c = colb >> 1;
                    float a = acc[mt][nf][half * 2 + 0] + __ldg(bias + c);
                    float g = acc[mt][nf][half * 2 + 1] + __ldg(bias + Hout + c);
                    float v = a * gelu_exact(g);
                    __nv_bfloat16 vh, vl; split_bf16(v, vh, vl);
                    size_t rr = ROUTED ? (size_t)(offE + row0 + ml) : (size_t)(row0 + ml);
                    OH[rr * Hout + c] = vh;
                    OL[rr * Hout + c] = vl;
                } else {
                    float v0 = acc[mt][nf][half * 2 + 0] + __ldg(bias + colb + 0);
                    float v1 = acc[mt][nf][half * 2 + 1] + __ldg(bias + colb + 1);
                    if constexpr (MODE == 2) {
                        int tok = sb_tok[ml];
                        float w = sb_w[ml];
                        float* op = C + (size_t)tok * N + colb;
                        atomicAdd(op + 0, w * v0);
                        atomicAdd(op + 1, w * v1);
                    } else if constexpr (MODE == 3) {
                        float* op = C + (size_t)(row0 + ml) * N + colb;
                        atomicAdd(op + 0, v0);
                        atomicAdd(op + 1, v1);
                    } else {
                        float2* cp = (float2*)(C + (size_t)(row0 + ml) * N + colb);
                        *cp = make_float2(v0, v1);
                    }
                }
            }
        }
    }
}

// ---------------- launch ----------------
extern "C" void kernel_launch(void* const* d_in, const int* in_sizes, int n_in,
                              void* d_out, int out_size) {
    const float* x   = (const float*)d_in[0];
    const float* Ws1 = (const float*)d_in[1];
    const float* bs1 = (const float*)d_in[2];
    const float* Ws2 = (const float*)d_in[3];
    const float* bs2 = (const float*)d_in[4];
    const float* We1 = (const float*)d_in[5];
    const float* be1 = (const float*)d_in[6];
    const float* We2 = (const float*)d_in[7];
    const float* be2 = (const float*)d_in[8];
    const float* Wr  = (const float*)d_in[9];
    const float* br  = (const float*)d_in[10];
    float* out = (float*)d_out;

    cudaFuncSetAttribute(fgemm<0, true>,  cudaFuncAttributeMaxDynamicSharedMemorySize, GSMEM);
    cudaFuncSetAttribute(fgemm<3, false>, cudaFuncAttributeMaxDynamicSharedMemorySize, GSMEM);
    cudaFuncSetAttribute(fgemm<1, true>,  cudaFuncAttributeMaxDynamicSharedMemorySize, GSMEM);
    cudaFuncSetAttribute(fgemm<2, false>, cudaFuncAttributeMaxDynamicSharedMemorySize, GSMEM);

    __nv_bfloat16 *p_xh, *p_xl, *p_ash, *p_asl, *p_arh, *p_arl;
    __nv_bfloat16 *p_w1h, *p_w1l, *p_w2h, *p_w2l, *p_e1h, *p_e1l, *p_e2h, *p_e2l;
    cudaGetSymbolAddress((void**)&p_xh, g_xh);   cudaGetSymbolAddress((void**)&p_xl, g_xl);
    cudaGetSymbolAddress((void**)&p_ash, g_ash); cudaGetSymbolAddress((void**)&p_asl, g_asl);
    cudaGetSymbolAddress((void**)&p_arh, g_arh); cudaGetSymbolAddress((void**)&p_arl, g_arl);
    cudaGetSymbolAddress((void**)&p_w1h, g_w1h); cudaGetSymbolAddress((void**)&p_w1l, g_w1l);
    cudaGetSymbolAddress((void**)&p_w2h, g_w2h); cudaGetSymbolAddress((void**)&p_w2l, g_w2l);
    cudaGetSymbolAddress((void**)&p_e1h, g_e1h); cudaGetSymbolAddress((void**)&p_e1l, g_e1l);
    cudaGetSymbolAddress((void**)&p_e2h, g_e2h); cudaGetSymbolAddress((void**)&p_e2l, g_e2l);

    // one-time host resources (streams/events only; no device alloc)
    static cudaStream_t sB = nullptr, sC = nullptr, sD = nullptr;
    static cudaEvent_t  evF = nullptr, evZ = nullptr, evW2 = nullptr, evD = nullptr;
    static cudaEvent_t  evG[NGRP] = {}, evQ[NGRP] = {};
    if (!sB) {
        cudaStreamCreateWithFlags(&sB, cudaStreamNonBlocking);
        cudaStreamCreateWithFlags(&sC, cudaStreamNonBlocking);
        cudaStreamCreateWithFlags(&sD, cudaStreamNonBlocking);
        cudaEventCreateWithFlags(&evF,  cudaEventDisableTiming);
        cudaEventCreateWithFlags(&evZ,  cudaEventDisableTiming);
        cudaEventCreateWithFlags(&evW2, cudaEventDisableTiming);
        cudaEventCreateWithFlags(&evD,  cudaEventDisableTiming);
        for (int g = 0; g < NGRP; g++) {
            cudaEventCreateWithFlags(&evG[g], cudaEventDisableTiming);
            cudaEventCreateWithFlags(&evQ[g], cudaEventDisableTiming);
        }
    }

    // --- origin: zero out, split x, zero counters; fork ---
    cudaMemsetAsync(out, 0, (size_t)NTOK * Dm * sizeof(float), 0);
    cudaEventRecord(evZ, 0);
    split_k<<<(NTOK * Dm / 4 + 255) / 256, 256>>>(
        (const float4*)x, (uint2*)p_xh, (uint2*)p_xl, NTOK * Dm / 4);
    zero_k<<<1, 32>>>();
    cudaEventRecord(evF, 0);
    cudaStreamWaitEvent(sB, evF, 0);
    cudaStreamWaitEvent(sC, evF, 0);

    // --- stream B: We1 conversion per group, then We2 conversion ---
    const size_t e1slab = (size_t)Dm * 2 * HRt;
    for (int g = 0; g < NGRP; g++) {
        wsplit_ilv_k<<<dim3((Dm * HRt + 255) / 256, EPG), 256, 0, sB>>>(
            We1 + (size_t)g * EPG * e1slab,
            p_e1h + (size_t)g * EPG * e1slab,
            p_e1l + (size_t)g * EPG * e1slab, Dm, HRt);
        cudaEventRecord(evG[g], sB);
    }
    split_k<<<(NEXP * HRt * Dm / 4 + 255) / 256, 256, 0, sB>>>(
        (const float4*)We2, (uint2*)p_e2h, (uint2*)p_e2l, NEXP * HRt * Dm / 4);
    cudaEventRecord(evW2, sB);

    // --- stream C: routing + routed GEMM1 per group ---
    router_k<<<NTOK, 128, 0, sC>>>(x, Wr, br);
    prefix_k<<<1, 1, 0, sC>>>();
    for (int g = 0; g < NGRP; g++) {
        cudaStreamWaitEvent(sC, evG[g], 0);
        fgemm<1, true><<<dim3(2 * HRt / 64, NTOK / 128, EPG), 256, GSMEM, sC>>>(
            p_xh, p_xl, p_e1h, p_e1l, be1, nullptr, p_arh, p_arl,
            0, 2 * HRt, Dm, g * EPG);
        cudaEventRecord(evQ[g], sC);
    }

    // --- stream D: routed GEMM2 per group (atomic add into out) ---
    cudaStreamWaitEvent(sD, evZ, 0);
    cudaStreamWaitEvent(sD, evW2, 0);
    for (int g = 0; g < NGRP; g++) {
        cudaStreamWaitEvent(sD, evQ[g], 0);
        fgemm<2, false><<<dim3(Dm / 64, NTOK / 128, EPG), 256, GSMEM, sD>>>(
            p_arh, p_arl, p_e2h, p_e2l, be2, out, nullptr, nullptr,
            0, Dm, HRt, g * EPG);
    }
    cudaEventRecord(evD, sD);

    // --- origin: shared expert path (accumulates into zeroed out) ---
    wsplit_ilv_k<<<dim3((Dm * HSh + 255) / 256, 1), 256>>>(
        Ws1, p_w1h, p_w1l, Dm, HSh);
    fgemm<0, true><<<dim3(2 * HSh / 64, NTOK / 128), 256, GSMEM>>>(
        p_xh, p_xl, p_w1h, p_w1l, bs1, nullptr, p_ash, p_asl, NTOK, 2 * HSh, Dm, 0);
    split_k<<<(HSh * Dm / 4 + 255) / 256, 256>>>(
        (const float4*)Ws2, (uint2*)p_w2h, (uint2*)p_w2l, HSh * Dm / 4);
    fgemm<3, false><<<dim3(Dm / 64, NTOK / 128), 256, GSMEM>>>(
        p_ash, p_asl, p_w2h, p_w2l, bs2, out, nullptr, nullptr, NTOK, Dm, HSh, 0);

    // --- join everything back to origin ---
    cudaStreamWaitEvent(0, evD, 0);
}

// round 15
// speedup vs baseline: 1.0393x; 1.0393x over previous
#include <cuda_runtime.h>
#include <cuda_bf16.h>
#include <math.h>
#include <stdint.h>

// ---------------- problem constants ----------------
static constexpr int NTOK = 2048;
static constexpr int Dm   = 1024;
static constexpr int NEXP = 12;
static constexpr int HSh  = 2048;   // shared hidden
static constexpr int HRt  = 3072;   // routed hidden
static constexpr float TAU = 1.5f;
static constexpr int NGRP = 3, EPG = NEXP / NGRP;   // expert pipeline groups

// ---------------- device scratch ----------------
__device__ int   g_cnt[NEXP];
__device__ int   g_off[NEXP];
__device__ int   g_bucket[NEXP * NTOK];
__device__ float g_bw[NEXP * NTOK];

__device__ __nv_bfloat16 g_xh[(size_t)NTOK * Dm],  g_xl[(size_t)NTOK * Dm];
__device__ __nv_bfloat16 g_ash[(size_t)NTOK * HSh], g_asl[(size_t)NTOK * HSh];
__device__ __nv_bfloat16 g_arh[(size_t)2 * NTOK * HRt], g_arl[(size_t)2 * NTOK * HRt];
// converted weights, SAME [K, N] layout as source (W1: a/g column-interleaved)
__device__ __nv_bfloat16 g_w1h[(size_t)Dm * 2 * HSh], g_w1l[(size_t)Dm * 2 * HSh];
__device__ __nv_bfloat16 g_w2h[(size_t)HSh * Dm],     g_w2l[(size_t)HSh * Dm];
__device__ __nv_bfloat16 g_e1h[(size_t)NEXP * Dm * 2 * HRt], g_e1l[(size_t)NEXP * Dm * 2 * HRt];
__device__ __nv_bfloat16 g_e2h[(size_t)NEXP * HRt * Dm],     g_e2l[(size_t)NEXP * HRt * Dm];

// ---------------- helpers ----------------
__device__ __forceinline__ uint32_t smem_u32(const void* p) {
    uint32_t a;
    asm("{ .reg .u64 t; cvta.to.shared.u64 t, %1; cvt.u32.u64 %0, t; }" : "=r"(a) : "l"(p));
    return a;
}
__device__ __forceinline__ uint32_t swzA(uint32_t b) { return b ^ ((b >> 3) & 0x70); }
// B tile: [32 k-rows][64 n-cols bf16] = 128B rows; 16B-granule xor swizzle
__device__ __forceinline__ uint32_t bofs(int k, int nb) {
    return (uint32_t)(k * 128 + (((nb >> 4) ^ (k & 7)) << 4) + (nb & 15));
}

__device__ __forceinline__ void cp16(uint32_t dst, const void* src, int sz) {
    asm volatile("cp.async.cg.shared.global [%0], [%1], 16, %2;"
                 :: "r"(dst), "l"(src), "r"(sz));
}
#define CP_COMMIT() asm volatile("cp.async.commit_group;" ::: "memory")

__device__ __forceinline__ void ldsm4(uint32_t* r, uint32_t addr) {
    asm volatile("ldmatrix.sync.aligned.m8n8.x4.shared.b16 {%0,%1,%2,%3}, [%4];"
                 : "=r"(r[0]), "=r"(r[1]), "=r"(r[2]), "=r"(r[3]) : "r"(addr));
}
__device__ __forceinline__ void ldsm4t(uint32_t* r, uint32_t addr) {
    asm volatile("ldmatrix.sync.aligned.m8n8.x4.trans.shared.b16 {%0,%1,%2,%3}, [%4];"
                 : "=r"(r[0]), "=r"(r[1]), "=r"(r[2]), "=r"(r[3]) : "r"(addr));
}
__device__ __forceinline__ void mma16816(float* c, const uint32_t* a, const uint32_t* b) {
    asm volatile(
        "mma.sync.aligned.m16n8k16.row.col.f32.bf16.bf16.f32 "
        "{%0,%1,%2,%3}, {%4,%5,%6,%7}, {%8,%9}, {%0,%1,%2,%3};"
        : "+f"(c[0]), "+f"(c[1]), "+f"(c[2]), "+f"(c[3])
        : "r"(a[0]), "r"(a[1]), "r"(a[2]), "r"(a[3]), "r"(b[0]), "r"(b[1]));
}
__device__ __forceinline__ void split_bf16(float v, __nv_bfloat16& h, __nv_bfloat16& l) {
    h = __float2bfloat16(v);
    l = __float2bfloat16(v - __bfloat162float(h));
}
__device__ __forceinline__ uint32_t pack2(__nv_bfloat16 a, __nv_bfloat16 b) {
    return (uint32_t)__bfloat16_as_ushort(a) | ((uint32_t)__bfloat16_as_ushort(b) << 16);
}
__device__ __forceinline__ float gelu_exact(float g) {
    return 0.5f * g * (1.0f + erff(g * 0.70710678118654752f));
}

// ---------------- tiny kernels ----------------
__global__ void zero_k() { if (threadIdx.x < NEXP) g_cnt[threadIdx.x] = 0; }

__global__ void prefix_k() {
    if (threadIdx.x == 0) {
        int s = 0;
        for (int e = 0; e < NEXP; e++) { g_off[e] = s; s += g_cnt[e]; }
    }
}

__global__ void router_k(const float* __restrict__ x,
                         const float* __restrict__ Wr,
                         const float* __restrict__ br) {
    int n = blockIdx.x, tid = threadIdx.x;            // 128 threads
    __shared__ float red[128 * NEXP];
    __shared__ float lg[NEXP];
    float part[NEXP];
#pragma unroll
    for (int e = 0; e < NEXP; e++) part[e] = 0.f;
    const float* xr = x + (size_t)n * Dm;
    for (int d = tid; d < Dm; d += 128) {
        float xv = xr[d];
        const float* wr = Wr + (size_t)d * NEXP;
#pragma unroll
        for (int e = 0; e < NEXP; e++) part[e] += xv * wr[e];
    }
#pragma unroll
    for (int e = 0; e < NEXP; e++) red[tid * NEXP + e] = part[e];
    __syncthreads();
    if (tid < NEXP) {
        float s = 0.f;
        for (int i = 0; i < 128; i++) s += red[i * NEXP + tid];
        lg[tid] = (s + br[tid]) / TAU;
    }
    __syncthreads();
    if (tid == 0) {
        int i0 = 0; float v0 = lg[0];
#pragma unroll
        for (int e = 1; e < NEXP; e++) if (lg[e] > v0) { v0 = lg[e]; i0 = e; }
        int i1 = -1; float v1 = -3.4e38f;
#pragma unroll
        for (int e = 0; e < NEXP; e++) if (e != i0 && lg[e] > v1) { v1 = lg[e]; i1 = e; }
        float e1 = __expf(v1 - v0);
        float inv = 1.f / (1.f + e1);
        int s0 = atomicAdd(&g_cnt[i0], 1);
        g_bucket[i0 * NTOK + s0] = n;  g_bw[i0 * NTOK + s0] = inv;
        int s1 = atomicAdd(&g_cnt[i1], 1);
        g_bucket[i1 * NTOK + s1] = n;  g_bw[i1 * NTOK + s1] = e1 * inv;
    }
}

// vectorized split fp32 -> bf16 hi/lo (layout-preserving, n multiple of 4)
__global__ void split_k(const float4* __restrict__ s, uint2* __restrict__ dh,
                        uint2* __restrict__ dl, int n4) {
    int i = blockIdx.x * 256 + threadIdx.x;
    if (i >= n4) return;
    float4 v = s[i];
    __nv_bfloat16 h[4], l[4];
    split_bf16(v.x, h[0], l[0]); split_bf16(v.y, h[1], l[1]);
    split_bf16(v.z, h[2], l[2]); split_bf16(v.w, h[3], l[3]);
    dh[i] = make_uint2(pack2(h[0], h[1]), pack2(h[2], h[3]));
    dl[i] = make_uint2(pack2(l[0], l[1]), pack2(l[2], l[3]));
}

// W1 conversion: fp32 [K, 2H] -> bf16 hi/lo [K, 2H] with a/g column interleave.
// 2D grid (no division): x covers H/4 per thread (float4), y = k, z = expert.
__global__ void wsplit_ilv_k(const float* __restrict__ W, __nv_bfloat16* __restrict__ oh,
                             __nv_bfloat16* __restrict__ ol, int K, int H) {
    int c = (blockIdx.x * 256 + threadIdx.x) * 4;
    if (c >= H) return;
    int k = blockIdx.y;
    size_t zo = (size_t)blockIdx.z * K * 2 * H;
    const float* wr = W + zo + (size_t)k * 2 * H;
    float4 av = *(const float4*)(wr + c);
    float4 gv = *(const float4*)(wr + H + c);
    __nv_bfloat16 ah[4], al[4], gh[4], gl[4];
    split_bf16(av.x, ah[0], al[0]); split_bf16(gv.x, gh[0], gl[0]);
    split_bf16(av.y, ah[1], al[1]); split_bf16(gv.y, gh[1], gl[1]);
    split_bf16(av.z, ah[2], al[2]); split_bf16(gv.z, gh[2], gl[2]);
    split_bf16(av.w, ah[3], al[3]); split_bf16(gv.w, gh[3], gl[3]);
    size_t o = zo + (size_t)k * 2 * H + 2 * c;     // 16B aligned
    *(uint4*)(oh + o) = make_uint4(pack2(ah[0], gh[0]), pack2(ah[1], gh[1]),
                                   pack2(ah[2], gh[2]), pack2(ah[3], gh[3]));
    *(uint4*)(ol + o) = make_uint4(pack2(al[0], gl[0]), pack2(al[1], gl[1]),
                                   pack2(al[2], gl[2]), pack2(al[3], gl[3]));
}

// ---------------- HMMA bf16x3 GEMM ----------------
// CTA 128M x 64N, 256 thr, 8 warps (4M x 2N), warp tile 32x32, 2 CTAs/SM.
// K-chunk 32, THREE smem stages, single __syncthreads per chunk.
// A stage: 128 rows x 128B, each row = [hi 64B | lo 64B], swzA (validated layout).
// B stage: hi/lo tiles of 32 k-rows x 128B, bofs swizzle (validated).
// MODE 0 plain store; MODE 1 A via bucket (expert=ebase+blockIdx.z), out row off[e]+m;
// MODE 2 A rows off[e]+m, atomicAdd(C[token], w*(acc+bias)).
static constexpr int A32_B  = 16384;                 // A stage (hi|lo packed)
static constexpr int B32_B  = 4096;                  // one B tile 32x64x2B
static constexpr int STG32  = A32_B + 2 * B32_B;     // 24576
static constexpr int GSMEM  = 3 * STG32;             // 73728

template <int MODE, bool GEGLU>
__global__ void __launch_bounds__(256, 2)
fgemm(const __nv_bfloat16* __restrict__ Ah, const __nv_bfloat16* __restrict__ Al,
      const __nv_bfloat16* __restrict__ Bh, const __nv_bfloat16* __restrict__ Bl,
      const float* __restrict__ bias, float* __restrict__ C,
      __nv_bfloat16* __restrict__ OH, __nv_bfloat16* __restrict__ OL,
      int M, int N, int K, int ebase) {
    extern __shared__ char sm[];
    __shared__ int   sb_tok[128];
    __shared__ float sb_w[128];

    const int tid = threadIdx.x, wid = tid >> 5, lane = tid & 31;
    const int wm = wid & 3, wn = wid >> 2;
    const int row0 = blockIdx.y * 128, col0 = blockIdx.x * 64;

    int e = 0, Me = M, offE = 0;
    if constexpr (MODE != 0) {
        e = ebase + blockIdx.z;
        Me = g_cnt[e];
        if (row0 >= Me) return;
        offE = g_off[e];
        Bh += (size_t)e * K * N;
        Bl += (size_t)e * K * N;
        bias += (size_t)e * N;
        if (tid < 128) {
            int r = row0 + tid;
            sb_tok[tid] = (r < Me) ? g_bucket[e * NTOK + r] : 0;
            sb_w[tid]   = (r < Me) ? g_bw[e * NTOK + r] : 0.f;
        }
        __syncthreads();
    }

    const int nch = K >> 5;
    const uint32_t smb = smem_u32(sm);

    auto issue_chunk = [&](int ck) {
        const int k0 = ck << 5;
        const uint32_t base = smb + (ck % 3) * STG32;
        // A (hi|lo packed rows): 1024 slots of 16B; cc<4 hi bytes, cc>=4 lo bytes
#pragma unroll
        for (int s = tid; s < 1024; s += 256) {
            int r = s >> 3, cc = s & 7;
            uint32_t dst = base + swzA((uint32_t)(r * 128 + cc * 16));
            const __nv_bfloat16* Ab = (cc < 4) ? Ah : Al;
            size_t ro = 0; int sz = 16;
            if constexpr (MODE == 1) {
                if (row0 + r < Me) ro = (size_t)sb_tok[r] * K; else sz = 0;
            } else if constexpr (MODE == 2) {
                if (row0 + r < Me) ro = (size_t)(offE + row0 + r) * K; else sz = 0;
            } else {
                ro = (size_t)(row0 + r) * K;
            }
            cp16(dst, Ab + ro + k0 + (cc & 3) * 8, sz);
        }
        // B hi/lo: 512 slots of 16B, 32 k-rows x 128B, bofs
#pragma unroll
        for (int s = tid; s < 512; s += 256) {
            int t = s >> 8, slot = s & 255;
            int k = slot >> 3, j16 = slot & 7;
            uint32_t dst = base + A32_B + t * B32_B + bofs(k, j16 * 16);
            const __nv_bfloat16* Bb = (t == 0) ? Bh : Bl;
            cp16(dst, Bb + (size_t)(k0 + k) * N + col0 + j16 * 8, 16);
        }
        CP_COMMIT();
    };

    float acc[2][4][4];
#pragma unroll
    for (int i = 0; i < 2; i++)
#pragma unroll
        for (int j = 0; j < 4; j++)
#pragma unroll
            for (int k = 0; k < 4; k++) acc[i][j][k] = 0.f;

    issue_chunk(0);
    issue_chunk(1);
    for (int ck = 0; ck < nch; ck++) {
        // chunk ck complete when <=1 newer group pending (or 0 at the last chunk)
        if (ck < nch - 1) asm volatile("cp.async.wait_group 1;" ::: "memory");
        else              asm volatile("cp.async.wait_group 0;" ::: "memory");
        __syncthreads();   // ck visible to all; all warps done computing ck-1
        if (ck + 2 < nch) issue_chunk(ck + 2);   // overwrites buffer of ck-1

        const uint32_t base = smb + (ck % 3) * STG32;
        const uint32_t tBh = base + A32_B, tBl = tBh + B32_B;

#pragma unroll
        for (int ks = 0; ks < 2; ks++) {
            uint32_t ahf[2][4], alf[2][4];
#pragma unroll
            for (int mt = 0; mt < 2; mt++) {
                int rrow = wm * 32 + mt * 16 + (lane & 15);
                uint32_t bcol = ks * 32 + (lane >> 4) * 16;
                ldsm4(ahf[mt], base + swzA((uint32_t)(rrow * 128 + bcol)));
                ldsm4(alf[mt], base + swzA((uint32_t)(rrow * 128 + 64 + bcol)));
            }
            const int sub = lane >> 3, i8 = lane & 7;
            const int kk = ks * 16 + (sub & 1) * 8 + i8;
            uint32_t bhf[4][2], blf[4][2];
#pragma unroll
            for (int g = 0; g < 2; g++) {
                int nn = wn * 32 + g * 16 + (sub >> 1) * 8;
                uint32_t byte = bofs(kk, nn * 2);
                uint32_t r4[4];
                ldsm4t(r4, tBh + byte);
                bhf[2 * g][0] = r4[0]; bhf[2 * g][1] = r4[1];
                bhf[2 * g + 1][0] = r4[2]; bhf[2 * g + 1][1] = r4[3];
                ldsm4t(r4, tBl + byte);
                blf[2 * g][0] = r4[0]; blf[2 * g][1] = r4[1];
                blf[2 * g + 1][0] = r4[2]; blf[2 * g + 1][1] = r4[3];
            }
#pragma unroll
            for (int mt = 0; mt < 2; mt++)
#pragma unroll
                for (int nf = 0; nf < 4; nf++) {
                    mma16816(acc[mt][nf], ahf[mt], bhf[nf]);
                    mma16816(acc[mt][nf], ahf[mt], blf[nf]);
                    mma16816(acc[mt][nf], alf[mt], bhf[nf]);
                }
        }
    }

    // ---------------- epilogue ----------------
    const int Hout = N >> 1;
#pragma unroll
    for (int mt = 0; mt < 2; mt++) {
#pragma unroll
        for (int half = 0; half < 2; half++) {
            int ml = wm * 32 + mt * 16 + (lane >> 2) + half * 8;
            if constexpr (MODE != 0) { if (row0 + ml >= Me) continue; }
#pragma unroll
            for (int nf = 0; nf < 4; nf++) {
                int colb = col0 + wn * 32 + nf * 8 + (lane & 3) * 2;
                if constexpr (GEGLU) {
                    int c = colb >> 1;
                    float a = acc[mt][nf][half * 2 + 0] + __ldg(bias + c);
                    float g = acc[mt][nf][half * 2 + 1] + __ldg(bias + Hout + c);
                    float v = a * gelu_exact(g);
                    __nv_bfloat16 vh, vl; split_bf16(v, vh, vl);
                    size_t rr = (MODE != 0) ? (size_t)(offE + row0 + ml)
                                            : (size_t)(row0 + ml);
                    OH[rr * Hout + c] = vh;
                    OL[rr * Hout + c] = vl;
                } else {
                    float v0 = acc[mt][nf][half * 2 + 0] + __ldg(bias + colb + 0);
                    float v1 = acc[mt][nf][half * 2 + 1] + __ldg(bias + colb + 1);
                    if constexpr (MODE == 2) {
                        int tok = sb_tok[ml];
                        float w = sb_w[ml];
                        float* op = C + (size_t)tok * N + colb;
                        atomicAdd(op + 0, w * v0);
                        atomicAdd(op + 1, w * v1);
                    } else {
                        float2* cp = (float2*)(C + (size_t)(row0 + ml) * N + colb);
                        *cp = make_float2(v0, v1);
                    }
                }
            }
        }
    }
}

// ---------------- launch ----------------
extern "C" void kernel_launch(void* const* d_in, const int* in_sizes, int n_in,
                              void* d_out, int out_size) {
    const float* x   = (const float*)d_in[0];
    const float* Ws1 = (const float*)d_in[1];
    const float* bs1 = (const float*)d_in[2];
    const float* Ws2 = (const float*)d_in[3];
    const float* bs2 = (const float*)d_in[4];
    const float* We1 = (const float*)d_in[5];
    const float* be1 = (const float*)d_in[6];
    const float* We2 = (const float*)d_in[7];
    const float* be2 = (const float*)d_in[8];
    const float* Wr  = (const float*)d_in[9];
    const float* br  = (const float*)d_in[10];
    float* out = (float*)d_out;

    cudaFuncSetAttribute(fgemm<0, true>,  cudaFuncAttributeMaxDynamicSharedMemorySize, GSMEM);
    cudaFuncSetAttribute(fgemm<0, false>, cudaFuncAttributeMaxDynamicSharedMemorySize, GSMEM);
    cudaFuncSetAttribute(fgemm<1, true>,  cudaFuncAttributeMaxDynamicSharedMemorySize, GSMEM);
    cudaFuncSetAttribute(fgemm<2, false>, cudaFuncAttributeMaxDynamicSharedMemorySize, GSMEM);

    __nv_bfloat16 *p_xh, *p_xl, *p_ash, *p_asl, *p_arh, *p_arl;
    __nv_bfloat16 *p_w1h, *p_w1l, *p_w2h, *p_w2l, *p_e1h, *p_e1l, *p_e2h, *p_e2l;
    cudaGetSymbolAddress((void**)&p_xh, g_xh);   cudaGetSymbolAddress((void**)&p_xl, g_xl);
    cudaGetSymbolAddress((void**)&p_ash, g_ash); cudaGetSymbolAddress((void**)&p_asl, g_asl);
    cudaGetSymbolAddress((void**)&p_arh, g_arh); cudaGetSymbolAddress((void**)&p_arl, g_arl);
    cudaGetSymbolAddress((void**)&p_w1h, g_w1h); cudaGetSymbolAddress((void**)&p_w1l, g_w1l);
    cudaGetSymbolAddress((void**)&p_w2h, g_w2h); cudaGetSymbolAddress((void**)&p_w2l, g_w2l);
    cudaGetSymbolAddress((void**)&p_e1h, g_e1h); cudaGetSymbolAddress((void**)&p_e1l, g_e1l);
    cudaGetSymbolAddress((void**)&p_e2h, g_e2h); cudaGetSymbolAddress((void**)&p_e2l, g_e2l);

    // one-time host resources (streams/events only; no device alloc)
    static cudaStream_t sB = nullptr, sC = nullptr;
    static cudaEvent_t  evF = nullptr, evJ = nullptr, evG[NGRP] = {};
    if (!sB) {
        cudaStreamCreateWithFlags(&sB, cudaStreamNonBlocking);
        cudaStreamCreateWithFlags(&sC, cudaStreamNonBlocking);
        cudaEventCreateWithFlags(&evF, cudaEventDisableTiming);
        cudaEventCreateWithFlags(&evJ, cudaEventDisableTiming);
        for (int g = 0; g < NGRP; g++)
            cudaEventCreateWithFlags(&evG[g], cudaEventDisableTiming);
    }

    // --- common prefix on origin stream ---
    split_k<<<(NTOK * Dm / 4 + 255) / 256, 256>>>(
        (const float4*)x, (uint2*)p_xh, (uint2*)p_xl, NTOK * Dm / 4);
    zero_k<<<1, 32>>>();
    cudaEventRecord(evF, 0);
    cudaStreamWaitEvent(sB, evF, 0);
    cudaStreamWaitEvent(sC, evF, 0);

    // --- stream B: We1 conversion in expert groups (feeds stream C) ---
    const size_t e1slab = (size_t)Dm * 2 * HRt;
    for (int g = 0; g < NGRP; g++) {
        wsplit_ilv_k<<<dim3((HRt / 4 + 255) / 256, Dm, EPG), 256, 0, sB>>>(
            We1 + (size_t)g * EPG * e1slab,
            p_e1h + (size_t)g * EPG * e1slab,
            p_e1l + (size_t)g * EPG * e1slab, Dm, HRt);
        cudaEventRecord(evG[g], sB);
    }

    // --- stream C: routing, then routed GEMM1 per group (pipelined vs conv) ---
    router_k<<<NTOK, 128, 0, sC>>>(x, Wr, br);
    prefix_k<<<1, 1, 0, sC>>>();
    for (int g = 0; g < NGRP; g++) {
        cudaStreamWaitEvent(sC, evG[g], 0);
        fgemm<1, true><<<dim3(2 * HRt / 64, NTOK / 128, EPG), 256, GSMEM, sC>>>(
            p_xh, p_xl, p_e1h, p_e1l, be1, nullptr, p_arh, p_arl,
            0, 2 * HRt, Dm, g * EPG);
    }
    cudaEventRecord(evJ, sC);

    // --- origin stream (branch A): shared expert path + We2 conversion ---
    wsplit_ilv_k<<<dim3((HSh / 4 + 255) / 256, Dm, 1), 256>>>(
        Ws1, p_w1h, p_w1l, Dm, HSh);
    fgemm<0, true><<<dim3(2 * HSh / 64, NTOK / 128), 256, GSMEM>>>(
        p_xh, p_xl, p_w1h, p_w1l, bs1, nullptr, p_ash, p_asl, NTOK, 2 * HSh, Dm, 0);
    split_k<<<(HSh * Dm / 4 + 255) / 256, 256>>>(
        (const float4*)Ws2, (uint2*)p_w2h, (uint2*)p_w2l, HSh * Dm / 4);
    fgemm<0, false><<<dim3(Dm / 64, NTOK / 128), 256, GSMEM>>>(
        p_ash, p_asl, p_w2h, p_w2l, bs2, out, nullptr, nullptr, NTOK, Dm, HSh, 0);
    split_k<<<(NEXP * HRt * Dm / 4 + 255) / 256, 256>>>(
        (const float4*)We2, (uint2*)p_e2h, (uint2*)p_e2l, NEXP * HRt * Dm / 4);

    // --- join: routed GEMM2 needs out + We2 (origin) and g_ar (stream C) ---
    cudaStreamWaitEvent(0, evJ, 0);
    fgemm<2, false><<<dim3(Dm / 64, NTOK / 128, NEXP), 256, GSMEM>>>(
        p_arh, p_arl, p_e2h, p_e2l, be2, out, nullptr, nullptr, 0, Dm, HRt, 0);
}

// round 16
// speedup vs baseline: 1.1352x; 1.0923x over previous
#include <cuda_runtime.h>
#include <cuda_bf16.h>
#include <math.h>
#include <stdint.h>

// ---------------- problem constants ----------------
static constexpr int NTOK = 2048;
static constexpr int Dm   = 1024;
static constexpr int NEXP = 12;
static constexpr int HSh  = 2048;   // shared hidden
static constexpr int HRt  = 3072;   // routed hidden
static constexpr float TAU = 1.5f;
static constexpr int NGRP = 3, EPG = NEXP / NGRP;   // expert pipeline groups

// ---------------- device scratch ----------------
__device__ int   g_cnt[NEXP];
__device__ int   g_off[NEXP];
__device__ int   g_bucket[NEXP * NTOK];
__device__ float g_bw[NEXP * NTOK];

__device__ __nv_bfloat16 g_xh[(size_t)NTOK * Dm],  g_xl[(size_t)NTOK * Dm];
__device__ __nv_bfloat16 g_ash[(size_t)NTOK * HSh], g_asl[(size_t)NTOK * HSh];
__device__ __nv_bfloat16 g_arh[(size_t)2 * NTOK * HRt], g_arl[(size_t)2 * NTOK * HRt];
// converted weights, SAME [K, N] layout as source (W1: a/g column-interleaved)
__device__ __nv_bfloat16 g_w1h[(size_t)Dm * 2 * HSh], g_w1l[(size_t)Dm * 2 * HSh];
__device__ __nv_bfloat16 g_w2h[(size_t)HSh * Dm],     g_w2l[(size_t)HSh * Dm];
__device__ __nv_bfloat16 g_e1h[(size_t)NEXP * Dm * 2 * HRt], g_e1l[(size_t)NEXP * Dm * 2 * HRt];
__device__ __nv_bfloat16 g_e2h[(size_t)NEXP * HRt * Dm],     g_e2l[(size_t)NEXP * HRt * Dm];

// ---------------- helpers ----------------
__device__ __forceinline__ uint32_t smem_u32(const void* p) {
    uint32_t a;
    asm("{ .reg .u64 t; cvta.to.shared.u64 t, %1; cvt.u32.u64 %0, t; }" : "=r"(a) : "l"(p));
    return a;
}
__device__ __forceinline__ uint32_t swzA(uint32_t b) { return b ^ ((b >> 3) & 0x70); }
// B tile: [64 k-rows][64 n-cols bf16] = 128B rows; 16B-granule xor swizzle
__device__ __forceinline__ uint32_t bofs(int k, int nb) {
    return (uint32_t)(k * 128 + (((nb >> 4) ^ (k & 7)) << 4) + (nb & 15));
}

__device__ __forceinline__ void cp16(uint32_t dst, const void* src, int sz) {
    asm volatile("cp.async.cg.shared.global [%0], [%1], 16, %2;"
                 :: "r"(dst), "l"(src), "r"(sz));
}
#define CP_COMMIT() asm volatile("cp.async.commit_group;" ::: "memory")

__device__ __forceinline__ void ldsm4(uint32_t* r, uint32_t addr) {
    asm volatile("ldmatrix.sync.aligned.m8n8.x4.shared.b16 {%0,%1,%2,%3}, [%4];"
                 : "=r"(r[0]), "=r"(r[1]), "=r"(r[2]), "=r"(r[3]) : "r"(addr));
}
__device__ __forceinline__ void ldsm4t(uint32_t* r, uint32_t addr) {
    asm volatile("ldmatrix.sync.aligned.m8n8.x4.trans.shared.b16 {%0,%1,%2,%3}, [%4];"
                 : "=r"(r[0]), "=r"(r[1]), "=r"(r[2]), "=r"(r[3]) : "r"(addr));
}
__device__ __forceinline__ void mma16816(float* c, const uint32_t* a, const uint32_t* b) {
    asm volatile(
        "mma.sync.aligned.m16n8k16.row.col.f32.bf16.bf16.f32 "
        "{%0,%1,%2,%3}, {%4,%5,%6,%7}, {%8,%9}, {%0,%1,%2,%3};"
        : "+f"(c[0]), "+f"(c[1]), "+f"(c[2]), "+f"(c[3])
        : "r"(a[0]), "r"(a[1]), "r"(a[2]), "r"(a[3]), "r"(b[0]), "r"(b[1]));
}
__device__ __forceinline__ void split_bf16(float v, __nv_bfloat16& h, __nv_bfloat16& l) {
    h = __float2bfloat16(v);
    l = __float2bfloat16(v - __bfloat162float(h));
}
__device__ __forceinline__ uint32_t pack2(__nv_bfloat16 a, __nv_bfloat16 b) {
    return (uint32_t)__bfloat16_as_ushort(a) | ((uint32_t)__bfloat16_as_ushort(b) << 16);
}
__device__ __forceinline__ float gelu_exact(float g) {
    return 0.5f * g * (1.0f + erff(g * 0.70710678118654752f));
}

// ---------------- tiny kernels ----------------
__global__ void zero_k() { if (threadIdx.x < NEXP) g_cnt[threadIdx.x] = 0; }

__global__ void prefix_k() {
    if (threadIdx.x == 0) {
        int s = 0;
        for (int e = 0; e < NEXP; e++) { g_off[e] = s; s += g_cnt[e]; }
    }
}

__global__ void router_k(const float* __restrict__ x,
                         const float* __restrict__ Wr,
                         const float* __restrict__ br) {
    int n = blockIdx.x, tid = threadIdx.x;            // 128 threads
    __shared__ float red[128 * NEXP];
    __shared__ float lg[NEXP];
    float part[NEXP];
#pragma unroll
    for (int e = 0; e < NEXP; e++) part[e] = 0.f;
    const float* xr = x + (size_t)n * Dm;
    for (int d = tid; d < Dm; d += 128) {
        float xv = xr[d];
        const float* wr = Wr + (size_t)d * NEXP;
#pragma unroll
        for (int e = 0; e < NEXP; e++) part[e] += xv * wr[e];
    }
#pragma unroll
    for (int e = 0; e < NEXP; e++) red[tid * NEXP + e] = part[e];
    __syncthreads();
    if (tid < NEXP) {
        float s = 0.f;
        for (int i = 0; i < 128; i++) s += red[i * NEXP + tid];
        lg[tid] = (s + br[tid]) / TAU;
    }
    __syncthreads();
    if (tid == 0) {
        int i0 = 0; float v0 = lg[0];
#pragma unroll
        for (int e = 1; e < NEXP; e++) if (lg[e] > v0) { v0 = lg[e]; i0 = e; }
        int i1 = -1; float v1 = -3.4e38f;
#pragma unroll
        for (int e = 0; e < NEXP; e++) if (e != i0 && lg[e] > v1) { v1 = lg[e]; i1 = e; }
        float e1 = __expf(v1 - v0);
        float inv = 1.f / (1.f + e1);
        int s0 = atomicAdd(&g_cnt[i0], 1);
        g_bucket[i0 * NTOK + s0] = n;  g_bw[i0 * NTOK + s0] = inv;
        int s1 = atomicAdd(&g_cnt[i1], 1);
        g_bucket[i1 * NTOK + s1] = n;  g_bw[i1 * NTOK + s1] = e1 * inv;
    }
}

// vectorized split fp32 -> bf16 hi/lo (layout-preserving, n multiple of 4)
__global__ void split_k(const float4* __restrict__ s, uint2* __restrict__ dh,
                        uint2* __restrict__ dl, int n4) {
    int i = blockIdx.x * 256 + threadIdx.x;
    if (i >= n4) return;
    float4 v = s[i];
    __nv_bfloat16 h[4], l[4];
    split_bf16(v.x, h[0], l[0]); split_bf16(v.y, h[1], l[1]);
    split_bf16(v.z, h[2], l[2]); split_bf16(v.w, h[3], l[3]);
    dh[i] = make_uint2(pack2(h[0], h[1]), pack2(h[2], h[3]));
    dl[i] = make_uint2(pack2(l[0], l[1]), pack2(l[2], l[3]));
}

// W1 conversion: fp32 [K, 2H] -> bf16 hi/lo [K, 2H] with a/g column interleave.
// 2D grid (no division): x covers H/4 per thread (float4), y = k, z = expert.
// (R15-validated: 69% DRAM, ~2x faster than the divide-based version.)
__global__ void wsplit_ilv_k(const float* __restrict__ W, __nv_bfloat16* __restrict__ oh,
                             __nv_bfloat16* __restrict__ ol, int K, int H) {
    int c = (blockIdx.x * 256 + threadIdx.x) * 4;
    if (c >= H) return;
    int k = blockIdx.y;
    size_t zo = (size_t)blockIdx.z * K * 2 * H;
    const float* wr = W + zo + (size_t)k * 2 * H;
    float4 av = *(const float4*)(wr + c);
    float4 gv = *(const float4*)(wr + H + c);
    __nv_bfloat16 ah[4], al[4], gh[4], gl[4];
    split_bf16(av.x, ah[0], al[0]); split_bf16(gv.x, gh[0], gl[0]);
    split_bf16(av.y, ah[1], al[1]); split_bf16(gv.y, gh[1], gl[1]);
    split_bf16(av.z, ah[2], al[2]); split_bf16(gv.z, gh[2], gl[2]);
    split_bf16(av.w, ah[3], al[3]); split_bf16(gv.w, gh[3], gl[3]);
    size_t o = zo + (size_t)k * 2 * H + 2 * c;     // 16B aligned
    *(uint4*)(oh + o) = make_uint4(pack2(ah[0], gh[0]), pack2(ah[1], gh[1]),
                                   pack2(ah[2], gh[2]), pack2(ah[3], gh[3]));
    *(uint4*)(ol + o) = make_uint4(pack2(al[0], gl[0]), pack2(al[1], gl[1]),
                                   pack2(al[2], gl[2]), pack2(al[3], gl[3]));
}

// ---------------- HMMA bf16x3 GEMM (R11-validated mainloop) ----------------
// CTA 128M x 64N, 256 thr, 8 warps (4M x 2N), warp tile 32x32, 2 CTAs/SM.
// K-chunk 64, 2-stage cp.async double buffering.
// A: bf16 hi/lo [M,K] (swzA, ldsm4). B: bf16 hi/lo [K,N] (bofs, ldsm4t).
// MODE 0 plain store; MODE 1 A via bucket (expert=ebase+blockIdx.z), out row off[e]+m;
// MODE 2 A rows off[e]+m, atomicAdd(C[token], w*(acc+bias)).
static constexpr int AT_B  = 16384;                 // A tile 128x64x2B
static constexpr int BT_B  = 8192;                  // B tile 64x64x2B
static constexpr int STG_B = 2 * AT_B + 2 * BT_B;   // 49152
static constexpr int GSMEM = 2 * STG_B;             // 98304

template <int MODE, bool GEGLU>
__global__ void __launch_bounds__(256, 2)
fgemm(const __nv_bfloat16* __restrict__ Ah, const __nv_bfloat16* __restrict__ Al,
      const __nv_bfloat16* __restrict__ Bh, const __nv_bfloat16* __restrict__ Bl,
      const float* __restrict__ bias, float* __restrict__ C,
      __nv_bfloat16* __restrict__ OH, __nv_bfloat16* __restrict__ OL,
      int M, int N, int K, int ebase) {
    extern __shared__ char sm[];
    __shared__ int   sb_tok[128];
    __shared__ float sb_w[128];

    const int tid = threadIdx.x, wid = tid >> 5, lane = tid & 31;
    const int wm = wid & 3, wn = wid >> 2;
    const int row0 = blockIdx.y * 128, col0 = blockIdx.x * 64;

    int e = 0, Me = M, offE = 0;
    if constexpr (MODE != 0) {
        e = ebase + blockIdx.z;
        Me = g_cnt[e];
        if (row0 >= Me) return;
        offE = g_off[e];
        Bh += (size_t)e * K * N;
        Bl += (size_t)e * K * N;
        bias += (size_t)e * N;
        if (tid < 128) {
            int r = row0 + tid;
            sb_tok[tid] = (r < Me) ? g_bucket[e * NTOK + r] : 0;
            sb_w[tid]   = (r < Me) ? g_bw[e * NTOK + r] : 0.f;
        }
        __syncthreads();
    }

    const int nch = K >> 6;
    const uint32_t smb = smem_u32(sm);

    auto issue_chunk = [&](int ck) {
        const int k0 = ck << 6;
        const uint32_t base = smb + (ck & 1) * STG_B;
#pragma unroll
        for (int s = tid; s < 2048; s += 256) {
            int t = s >> 10, slot = s & 1023;
            int r = slot >> 3, cc = slot & 7;
            uint32_t dst = base + t * AT_B + swzA((uint32_t)(r * 128 + cc * 16));
            const __nv_bfloat16* Ab = (t == 0) ? Ah : Al;
            size_t ro = 0; int sz = 16;
            if constexpr (MODE == 1) {
                if (row0 + r < Me) ro = (size_t)sb_tok[r] * K; else sz = 0;
            } else if constexpr (MODE == 2) {
                if (row0 + r < Me) ro = (size_t)(offE + row0 + r) * K; else sz = 0;
            } else {
                ro = (size_t)(row0 + r) * K;
            }
            cp16(dst, Ab + ro + k0 + cc * 8, sz);
        }
#pragma unroll
        for (int s = tid; s < 1024; s += 256) {
            int t = s >> 9, slot = s & 511;
            int k = slot >> 3, j16 = slot & 7;
            uint32_t dst = base + 2 * AT_B + t * BT_B + bofs(k, j16 * 16);
            const __nv_bfloat16* Bb = (t == 0) ? Bh : Bl;
            cp16(dst, Bb + (size_t)(k0 + k) * N + col0 + j16 * 8, 16);
        }
        CP_COMMIT();
    };

    float acc[2][4][4];
#pragma unroll
    for (int i = 0; i < 2; i++)
#pragma unroll
        for (int j = 0; j < 4; j++)
#pragma unroll
            for (int k = 0; k < 4; k++) acc[i][j][k] = 0.f;

    issue_chunk(0);
    for (int ck = 0; ck < nch; ck++) {
        if (ck + 1 < nch) {
            issue_chunk(ck + 1);
            asm volatile("cp.async.wait_group 1;" ::: "memory");
        } else {
            asm volatile("cp.async.wait_group 0;" ::: "memory");
        }
        __syncthreads();

        const uint32_t base = smb + (ck & 1) * STG_B;
        const uint32_t tAh = base, tAl = base + AT_B;
        const uint32_t tBh = base + 2 * AT_B, tBl = tBh + BT_B;

#pragma unroll
        for (int ks = 0; ks < 4; ks++) {
            uint32_t ahf[2][4], alf[2][4];
#pragma unroll
            for (int mt = 0; mt < 2; mt++) {
                int rrow = wm * 32 + mt * 16 + (lane & 15);
                uint32_t byte = swzA((uint32_t)(rrow * 128 + ks * 32 + (lane >> 4) * 16));
                ldsm4(ahf[mt], tAh + byte);
                ldsm4(alf[mt], tAl + byte);
            }
            const int sub = lane >> 3, i8 = lane & 7;
            const int kk = ks * 16 + (sub & 1) * 8 + i8;
            uint32_t bhf[4][2], blf[4][2];
#pragma unroll
            for (int g = 0; g < 2; g++) {
                int nn = wn * 32 + g * 16 + (sub >> 1) * 8;
                uint32_t byte = bofs(kk, nn * 2);
                uint32_t r4[4];
                ldsm4t(r4, tBh + byte);
                bhf[2 * g][0] = r4[0]; bhf[2 * g][1] = r4[1];
                bhf[2 * g + 1][0] = r4[2]; bhf[2 * g + 1][1] = r4[3];
                ldsm4t(r4, tBl + byte);
                blf[2 * g][0] = r4[0]; blf[2 * g][1] = r4[1];
                blf[2 * g + 1][0] = r4[2]; blf[2 * g + 1][1] = r4[3];
            }
#pragma unroll
            for (int mt = 0; mt < 2; mt++)
#pragma unroll
                for (int nf = 0; nf < 4; nf++) {
                    mma16816(acc[mt][nf], ahf[mt], bhf[nf]);
                    mma16816(acc[mt][nf], ahf[mt], blf[nf]);
                    mma16816(acc[mt][nf], alf[mt], bhf[nf]);
                }
        }
        __syncthreads();
    }

    // ---------------- epilogue ----------------
    const int Hout = N >> 1;
#pragma unroll
    for (int mt = 0; mt < 2; mt++) {
#pragma unroll
        for (int half = 0; half < 2; half++) {
            int ml = wm * 32 + mt * 16 + (lane >> 2) + half * 8;
            if constexpr (MODE != 0) { if (row0 + ml >= Me) continue; }
#pragma unroll
            for (int nf = 0; nf < 4; nf++) {
                int colb = col0 + wn * 32 + nf * 8 + (lane & 3) * 2;
                if constexpr (GEGLU) {
                    int c = colb >> 1;
                    float a = acc[mt][nf][half * 2 + 0] + __ldg(bias + c);
                    float g = acc[mt][nf][half * 2 + 1] + __ldg(bias + Hout + c);
                    float v = a * gelu_exact(g);
                    __nv_bfloat16 vh, vl; split_bf16(v, vh, vl);
                    size_t rr = (MODE != 0) ? (size_t)(offE + row0 + ml)
                                            : (size_t)(row0 + ml);
                    OH[rr * Hout + c] = vh;
                    OL[rr * Hout + c] = vl;
                } else {
                    float v0 = acc[mt][nf][half * 2 + 0] + __ldg(bias + colb + 0);
                    float v1 = acc[mt][nf][half * 2 + 1] + __ldg(bias + colb + 1);
                    if constexpr (MODE == 2) {
                        int tok = sb_tok[ml];
                        float w = sb_w[ml];
                        float* op = C + (size_t)tok * N + colb;
                        atomicAdd(op + 0, w * v0);
                        atomicAdd(op + 1, w * v1);
                    } else {
                        float2* cp = (float2*)(C + (size_t)(row0 + ml) * N + colb);
                        *cp = make_float2(v0, v1);
                    }
                }
            }
        }
    }
}

// ---------------- launch ----------------
extern "C" void kernel_launch(void* const* d_in, const int* in_sizes, int n_in,
                              void* d_out, int out_size) {
    const float* x   = (const float*)d_in[0];
    const float* Ws1 = (const float*)d_in[1];
    const float* bs1 = (const float*)d_in[2];
    const float* Ws2 = (const float*)d_in[3];
    const float* bs2 = (const float*)d_in[4];
    const float* We1 = (const float*)d_in[5];
    const float* be1 = (const float*)d_in[6];
    const float* We2 = (const float*)d_in[7];
    const float* be2 = (const float*)d_in[8];
    const float* Wr  = (const float*)d_in[9];
    const float* br  = (const float*)d_in[10];
    float* out = (float*)d_out;

    cudaFuncSetAttribute(fgemm<0, true>,  cudaFuncAttributeMaxDynamicSharedMemorySize, GSMEM);
    cudaFuncSetAttribute(fgemm<0, false>, cudaFuncAttributeMaxDynamicSharedMemorySize, GSMEM);
    cudaFuncSetAttribute(fgemm<1, true>,  cudaFuncAttributeMaxDynamicSharedMemorySize, GSMEM);
    cudaFuncSetAttribute(fgemm<2, false>, cudaFuncAttributeMaxDynamicSharedMemorySize, GSMEM);

    __nv_bfloat16 *p_xh, *p_xl, *p_ash, *p_asl, *p_arh, *p_arl;
    __nv_bfloat16 *p_w1h, *p_w1l, *p_w2h, *p_w2l, *p_e1h, *p_e1l, *p_e2h, *p_e2l;
    cudaGetSymbolAddress((void**)&p_xh, g_xh);   cudaGetSymbolAddress((void**)&p_xl, g_xl);
    cudaGetSymbolAddress((void**)&p_ash, g_ash); cudaGetSymbolAddress((void**)&p_asl, g_asl);
    cudaGetSymbolAddress((void**)&p_arh, g_arh); cudaGetSymbolAddress((void**)&p_arl, g_arl);
    cudaGetSymbolAddress((void**)&p_w1h, g_w1h); cudaGetSymbolAddress((void**)&p_w1l, g_w1l);
    cudaGetSymbolAddress((void**)&p_w2h, g_w2h); cudaGetSymbolAddress((void**)&p_w2l, g_w2l);
    cudaGetSymbolAddress((void**)&p_e1h, g_e1h); cudaGetSymbolAddress((void**)&p_e1l, g_e1l);
    cudaGetSymbolAddress((void**)&p_e2h, g_e2h); cudaGetSymbolAddress((void**)&p_e2l, g_e2l);

    // one-time host resources (streams/events only; no device alloc)
    static cudaStream_t sB = nullptr, sC = nullptr;
    static cudaEvent_t  evF = nullptr, evJ = nullptr, evG[NGRP] = {};
    if (!sB) {
        cudaStreamCreateWithFlags(&sB, cudaStreamNonBlocking);
        cudaStreamCreateWithFlags(&sC, cudaStreamNonBlocking);
        cudaEventCreateWithFlags(&evF, cudaEventDisableTiming);
        cudaEventCreateWithFlags(&evJ, cudaEventDisableTiming);
        for (int g = 0; g < NGRP; g++)
            cudaEventCreateWithFlags(&evG[g], cudaEventDisableTiming);
    }

    // --- common prefix on origin stream ---
    split_k<<<(NTOK * Dm / 4 + 255) / 256, 256>>>(
        (const float4*)x, (uint2*)p_xh, (uint2*)p_xl, NTOK * Dm / 4);
    zero_k<<<1, 32>>>();
    cudaEventRecord(evF, 0);
    cudaStreamWaitEvent(sB, evF, 0);
    cudaStreamWaitEvent(sC, evF, 0);

    // --- stream B: We1 conversion in expert groups (feeds stream C) ---
    const size_t e1slab = (size_t)Dm * 2 * HRt;
    for (int g = 0; g < NGRP; g++) {
        wsplit_ilv_k<<<dim3((HRt / 4 + 255) / 256, Dm, EPG), 256, 0, sB>>>(
            We1 + (size_t)g * EPG * e1slab,
            p_e1h + (size_t)g * EPG * e1slab,
            p_e1l + (size_t)g * EPG * e1slab, Dm, HRt);
        cudaEventRecord(evG[g], sB);
    }

    // --- stream C: routing, then routed GEMM1 per group (pipelined vs conv) ---
    router_k<<<NTOK, 128, 0, sC>>>(x, Wr, br);
    prefix_k<<<1, 1, 0, sC>>>();
    for (int g = 0; g < NGRP; g++) {
        cudaStreamWaitEvent(sC, evG[g], 0);
        fgemm<1, true><<<dim3(2 * HRt / 64, NTOK / 128, EPG), 256, GSMEM, sC>>>(
            p_xh, p_xl, p_e1h, p_e1l, be1, nullptr, p_arh, p_arl,
            0, 2 * HRt, Dm, g * EPG);
    }
    cudaEventRecord(evJ, sC);

    // --- origin stream (branch A): shared expert path + We2 conversion ---
    wsplit_ilv_k<<<dim3((HSh / 4 + 255) / 256, Dm, 1), 256>>>(
        Ws1, p_w1h, p_w1l, Dm, HSh);
    fgemm<0, true><<<dim3(2 * HSh / 64, NTOK / 128), 256, GSMEM>>>(
        p_xh, p_xl, p_w1h, p_w1l, bs1, nullptr, p_ash, p_asl, NTOK, 2 * HSh, Dm, 0);
    split_k<<<(HSh * Dm / 4 + 255) / 256, 256>>>(
        (const float4*)Ws2, (uint2*)p_w2h, (uint2*)p_w2l, HSh * Dm / 4);
    fgemm<0, false><<<dim3(Dm / 64, NTOK / 128), 256, GSMEM>>>(
        p_ash, p_asl, p_w2h, p_w2l, bs2, out, nullptr, nullptr, NTOK, Dm, HSh, 0);
    split_k<<<(NEXP * HRt * Dm / 4 + 255) / 256, 256>>>(
        (const float4*)We2, (uint2*)p_e2h, (uint2*)p_e2l, NEXP * HRt * Dm / 4);

    // --- join: routed GEMM2 needs out + We2 (origin) and g_ar (stream C) ---
    cudaStreamWaitEvent(0, evJ, 0);
    fgemm<2, false><<<dim3(Dm / 64, NTOK / 128, NEXP), 256, GSMEM>>>(
        p_arh, p_arl, p_e2h, p_e2l, be2, out, nullptr, nullptr, 0, Dm, HRt, 0);
}

// round 17
// speedup vs baseline: 1.5105x; 1.3307x over previous
#include <cuda_runtime.h>
#include <cuda_fp16.h>
#include <math.h>
#include <stdint.h>

// ---------------- problem constants ----------------
static constexpr int NTOK = 2048;
static constexpr int Dm   = 1024;
static constexpr int NEXP = 12;
static constexpr int HSh  = 2048;   // shared hidden
static constexpr int HRt  = 3072;   // routed hidden
static constexpr float TAU = 1.5f;
static constexpr int NGRP = 3, EPG = NEXP / NGRP;   // expert pipeline groups

// ---------------- device scratch ----------------
__device__ int   g_cnt[NEXP];
__device__ int   g_off[NEXP];
__device__ int   g_bucket[NEXP * NTOK];
__device__ float g_bw[NEXP * NTOK];

// activations: fp16 hi/lo (exact 2-term split)
__device__ __half g_xh[(size_t)NTOK * Dm],  g_xl[(size_t)NTOK * Dm];
__device__ __half g_ash[(size_t)NTOK * HSh], g_asl[(size_t)NTOK * HSh];
__device__ __half g_arh[(size_t)2 * NTOK * HRt], g_arl[(size_t)2 * NTOK * HRt];
// weights: SINGLE fp16, same [K, N] layout as source (W1: a/g column-interleaved)
__device__ __half g_w1[(size_t)Dm * 2 * HSh];
__device__ __half g_w2[(size_t)HSh * Dm];
__device__ __half g_e1[(size_t)NEXP * Dm * 2 * HRt];
__device__ __half g_e2[(size_t)NEXP * HRt * Dm];

// ---------------- helpers ----------------
__device__ __forceinline__ uint32_t smem_u32(const void* p) {
    uint32_t a;
    asm("{ .reg .u64 t; cvta.to.shared.u64 t, %1; cvt.u32.u64 %0, t; }" : "=r"(a) : "l"(p));
    return a;
}
__device__ __forceinline__ uint32_t swzA(uint32_t b) { return b ^ ((b >> 3) & 0x70); }
// B tile: [64 k-rows][64 n-cols fp16] = 128B rows; 16B-granule xor swizzle
__device__ __forceinline__ uint32_t bofs(int k, int nb) {
    return (uint32_t)(k * 128 + (((nb >> 4) ^ (k & 7)) << 4) + (nb & 15));
}

__device__ __forceinline__ void cp16(uint32_t dst, const void* src, int sz) {
    asm volatile("cp.async.cg.shared.global [%0], [%1], 16, %2;"
                 :: "r"(dst), "l"(src), "r"(sz));
}
#define CP_COMMIT() asm volatile("cp.async.commit_group;" ::: "memory")

__device__ __forceinline__ void ldsm4(uint32_t* r, uint32_t addr) {
    asm volatile("ldmatrix.sync.aligned.m8n8.x4.shared.b16 {%0,%1,%2,%3}, [%4];"
                 : "=r"(r[0]), "=r"(r[1]), "=r"(r[2]), "=r"(r[3]) : "r"(addr));
}
__device__ __forceinline__ void ldsm4t(uint32_t* r, uint32_t addr) {
    asm volatile("ldmatrix.sync.aligned.m8n8.x4.trans.shared.b16 {%0,%1,%2,%3}, [%4];"
                 : "=r"(r[0]), "=r"(r[1]), "=r"(r[2]), "=r"(r[3]) : "r"(addr));
}
__device__ __forceinline__ void mma16816(float* c, const uint32_t* a, const uint32_t* b) {
    asm volatile(
        "mma.sync.aligned.m16n8k16.row.col.f32.f16.f16.f32 "
        "{%0,%1,%2,%3}, {%4,%5,%6,%7}, {%8,%9}, {%0,%1,%2,%3};"
        : "+f"(c[0]), "+f"(c[1]), "+f"(c[2]), "+f"(c[3])
        : "r"(a[0]), "r"(a[1]), "r"(a[2]), "r"(a[3]), "r"(b[0]), "r"(b[1]));
}
__device__ __forceinline__ void split_fp16(float v, __half& h, __half& l) {
    h = __float2half_rn(v);
    l = __float2half_rn(v - __half2float(h));
}
__device__ __forceinline__ uint32_t pack2h(__half a, __half b) {
    return (uint32_t)__half_as_ushort(a) | ((uint32_t)__half_as_ushort(b) << 16);
}
__device__ __forceinline__ float gelu_exact(float g) {
    return 0.5f * g * (1.0f + erff(g * 0.70710678118654752f));
}

// ---------------- tiny kernels ----------------
__global__ void zero_k() { if (threadIdx.x < NEXP) g_cnt[threadIdx.x] = 0; }

__global__ void prefix_k() {
    if (threadIdx.x == 0) {
        int s = 0;
        for (int e = 0; e < NEXP; e++) { g_off[e] = s; s += g_cnt[e]; }
    }
}

__global__ void router_k(const float* __restrict__ x,
                         const float* __restrict__ Wr,
                         const float* __restrict__ br) {
    int n = blockIdx.x, tid = threadIdx.x;            // 128 threads
    __shared__ float red[128 * NEXP];
    __shared__ float lg[NEXP];
    float part[NEXP];
#pragma unroll
    for (int e = 0; e < NEXP; e++) part[e] = 0.f;
    const float* xr = x + (size_t)n * Dm;
    for (int d = tid; d < Dm; d += 128) {
        float xv = xr[d];
        const float* wr = Wr + (size_t)d * NEXP;
#pragma unroll
        for (int e = 0; e < NEXP; e++) part[e] += xv * wr[e];
    }
#pragma unroll
    for (int e = 0; e < NEXP; e++) red[tid * NEXP + e] = part[e];
    __syncthreads();
    if (tid < NEXP) {
        float s = 0.f;
        for (int i = 0; i < 128; i++) s += red[i * NEXP + tid];
        lg[tid] = (s + br[tid]) / TAU;
    }
    __syncthreads();
    if (tid == 0) {
        int i0 = 0; float v0 = lg[0];
#pragma unroll
        for (int e = 1; e < NEXP; e++) if (lg[e] > v0) { v0 = lg[e]; i0 = e; }
        int i1 = -1; float v1 = -3.4e38f;
#pragma unroll
        for (int e = 0; e < NEXP; e++) if (e != i0 && lg[e] > v1) { v1 = lg[e]; i1 = e; }
        float e1 = __expf(v1 - v0);
        float inv = 1.f / (1.f + e1);
        int s0 = atomicAdd(&g_cnt[i0], 1);
        g_bucket[i0 * NTOK + s0] = n;  g_bw[i0 * NTOK + s0] = inv;
        int s1 = atomicAdd(&g_cnt[i1], 1);
        g_bucket[i1 * NTOK + s1] = n;  g_bw[i1 * NTOK + s1] = e1 * inv;
    }
}

// split fp32 -> fp16 hi/lo (activations; layout-preserving)
__global__ void split2_k(const float4* __restrict__ s, uint2* __restrict__ dh,
                         uint2* __restrict__ dl, int n4) {
    int i = blockIdx.x * 256 + threadIdx.x;
    if (i >= n4) return;
    float4 v = s[i];
    __half h[4], l[4];
    split_fp16(v.x, h[0], l[0]); split_fp16(v.y, h[1], l[1]);
    split_fp16(v.z, h[2], l[2]); split_fp16(v.w, h[3], l[3]);
    dh[i] = make_uint2(pack2h(h[0], h[1]), pack2h(h[2], h[3]));
    dl[i] = make_uint2(pack2h(l[0], l[1]), pack2h(l[2], l[3]));
}

// plain fp32 -> fp16 convert (weights; layout-preserving)
__global__ void conv1_k(const float4* __restrict__ s, uint2* __restrict__ d, int n4) {
    int i = blockIdx.x * 256 + threadIdx.x;
    if (i >= n4) return;
    float4 v = s[i];
    d[i] = make_uint2(pack2h(__float2half_rn(v.x), __float2half_rn(v.y)),
                      pack2h(__float2half_rn(v.z), __float2half_rn(v.w)));
}

// W1 conversion: fp32 [K, 2H] -> fp16 [K, 2H] with a/g column interleave.
// 2D grid: x covers H/4 per thread (float4), y = k, z = expert.
__global__ void wconv_ilv_k(const float* __restrict__ W, __half* __restrict__ o,
                            int K, int H) {
    int c = (blockIdx.x * 256 + threadIdx.x) * 4;
    if (c >= H) return;
    int k = blockIdx.y;
    size_t zo = (size_t)blockIdx.z * K * 2 * H;
    const float* wr = W + zo + (size_t)k * 2 * H;
    float4 av = *(const float4*)(wr + c);
    float4 gv = *(const float4*)(wr + H + c);
    size_t off = zo + (size_t)k * 2 * H + 2 * c;     // 16B aligned
    *(uint4*)(o + off) = make_uint4(
        pack2h(__float2half_rn(av.x), __float2half_rn(gv.x)),
        pack2h(__float2half_rn(av.y), __float2half_rn(gv.y)),
        pack2h(__float2half_rn(av.z), __float2half_rn(gv.z)),
        pack2h(__float2half_rn(av.w), __float2half_rn(gv.w)));
}

// ---------------- HMMA fp16x2 GEMM (asymmetric split) ----------------
// D = (Ah + Al) @ Bh  — exact in A, fp16-quantized in B only.
// CTA 128M x 64N, 256 thr, 8 warps (4M x 2N), warp tile 32x32, 2 CTAs/SM.
// K-chunk 64, 2-stage cp.async. A: fp16 hi/lo [M,K] (swzA, ldsm4).
// B: single fp16 [K,N] (bofs, ldsm4t).
// MODE 0 plain store; MODE 1 A via bucket (expert=ebase+blockIdx.z), out row off[e]+m;
// MODE 2 A rows off[e]+m, atomicAdd(C[token], w*(acc+bias)).
static constexpr int AT_B  = 16384;                 // A tile 128x64x2B
static constexpr int BT_B  = 8192;                  // B tile 64x64x2B
static constexpr int STG_B = 2 * AT_B + BT_B;       // 40960
static constexpr int GSMEM = 2 * STG_B;             // 81920

template <int MODE, bool GEGLU>
__global__ void __launch_bounds__(256, 2)
fgemm(const __half* __restrict__ Ah, const __half* __restrict__ Al,
      const __half* __restrict__ B, const float* __restrict__ bias,
      float* __restrict__ C, __half* __restrict__ OH, __half* __restrict__ OL,
      int M, int N, int K, int ebase) {
    extern __shared__ char sm[];
    __shared__ int   sb_tok[128];
    __shared__ float sb_w[128];

    const int tid = threadIdx.x, wid = tid >> 5, lane = tid & 31;
    const int wm = wid & 3, wn = wid >> 2;
    const int row0 = blockIdx.y * 128, col0 = blockIdx.x * 64;

    int e = 0, Me = M, offE = 0;
    if constexpr (MODE != 0) {
        e = ebase + blockIdx.z;
        Me = g_cnt[e];
        if (row0 >= Me) return;
        offE = g_off[e];
        B    += (size_t)e * K * N;
        bias += (size_t)e * N;
        if (tid < 128) {
            int r = row0 + tid;
            sb_tok[tid] = (r < Me) ? g_bucket[e * NTOK + r] : 0;
            sb_w[tid]   = (r < Me) ? g_bw[e * NTOK + r] : 0.f;
        }
        __syncthreads();
    }

    const int nch = K >> 6;
    const uint32_t smb = smem_u32(sm);

    auto issue_chunk = [&](int ck) {
        const int k0 = ck << 6;
        const uint32_t base = smb + (ck & 1) * STG_B;
        // A tiles (hi/lo): 2048 slots of 16B, 128 rows x 128B, swzA
#pragma unroll
        for (int s = tid; s < 2048; s += 256) {
            int t = s >> 10, slot = s & 1023;
            int r = slot >> 3, cc = slot & 7;
            uint32_t dst = base + t * AT_B + swzA((uint32_t)(r * 128 + cc * 16));
            const __half* Ab = (t == 0) ? Ah : Al;
            size_t ro = 0; int sz = 16;
            if constexpr (MODE == 1) {
                if (row0 + r < Me) ro = (size_t)sb_tok[r] * K; else sz = 0;
            } else if constexpr (MODE == 2) {
                if (row0 + r < Me) ro = (size_t)(offE + row0 + r) * K; else sz = 0;
            } else {
                ro = (size_t)(row0 + r) * K;
            }
            cp16(dst, Ab + ro + k0 + cc * 8, sz);
        }
        // B tile (single): 512 slots of 16B, 64 k-rows x 128B, bofs
#pragma unroll
        for (int s = tid; s < 512; s += 256) {
            int k = s >> 3, j16 = s & 7;
            uint32_t dst = base + 2 * AT_B + bofs(k, j16 * 16);
            cp16(dst, B + (size_t)(k0 + k) * N + col0 + j16 * 8, 16);
        }
        CP_COMMIT();
    };

    float acc[2][4][4];
#pragma unroll
    for (int i = 0; i < 2; i++)
#pragma unroll
        for (int j = 0; j < 4; j++)
#pragma unroll
            for (int k = 0; k < 4; k++) acc[i][j][k] = 0.f;

    issue_chunk(0);
    for (int ck = 0; ck < nch; ck++) {
        if (ck + 1 < nch) {
            issue_chunk(ck + 1);
            asm volatile("cp.async.wait_group 1;" ::: "memory");
        } else {
            asm volatile("cp.async.wait_group 0;" ::: "memory");
        }
        __syncthreads();

        const uint32_t base = smb + (ck & 1) * STG_B;
        const uint32_t tAh = base, tAl = base + AT_B;
        const uint32_t tB  = base + 2 * AT_B;

#pragma unroll
        for (int ks = 0; ks < 4; ks++) {
            uint32_t ahf[2][4], alf[2][4];
#pragma unroll
            for (int mt = 0; mt < 2; mt++) {
                int rrow = wm * 32 + mt * 16 + (lane & 15);
                uint32_t byte = swzA((uint32_t)(rrow * 128 + ks * 32 + (lane >> 4) * 16));
                ldsm4(ahf[mt], tAh + byte);
                ldsm4(alf[mt], tAl + byte);
            }
            const int sub = lane >> 3, i8 = lane & 7;
            const int kk = ks * 16 + (sub & 1) * 8 + i8;
            uint32_t bhf[4][2];
#pragma unroll
            for (int g = 0; g < 2; g++) {
                int nn = wn * 32 + g * 16 + (sub >> 1) * 8;
                uint32_t byte = bofs(kk, nn * 2);
                uint32_t r4[4];
                ldsm4t(r4, tB + byte);
                bhf[2 * g][0] = r4[0]; bhf[2 * g][1] = r4[1];
                bhf[2 * g + 1][0] = r4[2]; bhf[2 * g + 1][1] = r4[3];
            }
#pragma unroll
            for (int mt = 0; mt < 2; mt++)
#pragma unroll
                for (int nf = 0; nf < 4; nf++) {
                    mma16816(acc[mt][nf], ahf[mt], bhf[nf]);
                    mma16816(acc[mt][nf], alf[mt], bhf[nf]);
                }
        }
        __syncthreads();
    }

    // ---------------- epilogue ----------------
    const int Hout = N >> 1;
#pragma unroll
    for (int mt = 0; mt < 2; mt++) {
#pragma unroll
        for (int half = 0; half < 2; half++) {
            int ml = wm * 32 + mt * 16 + (lane >> 2) + half * 8;
            if constexpr (MODE != 0) { if (row0 + ml >= Me) continue; }
#pragma unroll
            for (int nf = 0; nf < 4; nf++) {
                int colb = col0 + wn * 32 + nf * 8 + (lane & 3) * 2;
                if constexpr (GEGLU) {
                    int c = colb >> 1;
                    float a = acc[mt][nf][half * 2 + 0] + __ldg(bias + c);
                    float g = acc[mt][nf][half * 2 + 1] + __ldg(bias + Hout + c);
                    float v = a * gelu_exact(g);
                    __half vh, vl; split_fp16(v, vh, vl);
                    size_t rr = (MODE != 0) ? (size_t)(offE + row0 + ml)
                                            : (size_t)(row0 + ml);
                    OH[rr * Hout + c] = vh;
                    OL[rr * Hout + c] = vl;
                } else {
                    float v0 = acc[mt][nf][half * 2 + 0] + __ldg(bias + colb + 0);
                    float v1 = acc[mt][nf][half * 2 + 1] + __ldg(bias + colb + 1);
                    if constexpr (MODE == 2) {
                        int tok = sb_tok[ml];
                        float w = sb_w[ml];
                        float* op = C + (size_t)tok * N + colb;
                        atomicAdd(op + 0, w * v0);
                        atomicAdd(op + 1, w * v1);
                    } else {
                        float2* cp = (float2*)(C + (size_t)(row0 + ml) * N + colb);
                        *cp = make_float2(v0, v1);
                    }
                }
            }
        }
    }
}

// ---------------- launch ----------------
extern "C" void kernel_launch(void* const* d_in, const int* in_sizes, int n_in,
                              void* d_out, int out_size) {
    const float* x   = (const float*)d_in[0];
    const float* Ws1 = (const float*)d_in[1];
    const float* bs1 = (const float*)d_in[2];
    const float* Ws2 = (const float*)d_in[3];
    const float* bs2 = (const float*)d_in[4];
    const float* We1 = (const float*)d_in[5];
    const float* be1 = (const float*)d_in[6];
    const float* We2 = (const float*)d_in[7];
    const float* be2 = (const float*)d_in[8];
    const float* Wr  = (const float*)d_in[9];
    const float* br  = (const float*)d_in[10];
    float* out = (float*)d_out;

    cudaFuncSetAttribute(fgemm<0, true>,  cudaFuncAttributeMaxDynamicSharedMemorySize, GSMEM);
    cudaFuncSetAttribute(fgemm<0, false>, cudaFuncAttributeMaxDynamicSharedMemorySize, GSMEM);
    cudaFuncSetAttribute(fgemm<1, true>,  cudaFuncAttributeMaxDynamicSharedMemorySize, GSMEM);
    cudaFuncSetAttribute(fgemm<2, false>, cudaFuncAttributeMaxDynamicSharedMemorySize, GSMEM);

    __half *p_xh, *p_xl, *p_ash, *p_asl, *p_arh, *p_arl;
    __half *p_w1, *p_w2, *p_e1, *p_e2;
    cudaGetSymbolAddress((void**)&p_xh, g_xh);   cudaGetSymbolAddress((void**)&p_xl, g_xl);
    cudaGetSymbolAddress((void**)&p_ash, g_ash); cudaGetSymbolAddress((void**)&p_asl, g_asl);
    cudaGetSymbolAddress((void**)&p_arh, g_arh); cudaGetSymbolAddress((void**)&p_arl, g_arl);
    cudaGetSymbolAddress((void**)&p_w1, g_w1);   cudaGetSymbolAddress((void**)&p_w2, g_w2);
    cudaGetSymbolAddress((void**)&p_e1, g_e1);   cudaGetSymbolAddress((void**)&p_e2, g_e2);

    // one-time host resources (streams/events only; no device alloc)
    static cudaStream_t sB = nullptr, sC = nullptr;
    static cudaEvent_t  evF = nullptr, evJ = nullptr, evG[NGRP] = {};
    if (!sB) {
        cudaStreamCreateWithFlags(&sB, cudaStreamNonBlocking);
        cudaStreamCreateWithFlags(&sC, cudaStreamNonBlocking);
        cudaEventCreateWithFlags(&evF, cudaEventDisableTiming);
        cudaEventCreateWithFlags(&evJ, cudaEventDisableTiming);
        for (int g = 0; g < NGRP; g++)
            cudaEventCreateWithFlags(&evG[g], cudaEventDisableTiming);
    }

    // --- common prefix on origin stream ---
    split2_k<<<(NTOK * Dm / 4 + 255) / 256, 256>>>(
        (const float4*)x, (uint2*)p_xh, (uint2*)p_xl, NTOK * Dm / 4);
    zero_k<<<1, 32>>>();
    cudaEventRecord(evF, 0);
    cudaStreamWaitEvent(sB, evF, 0);
    cudaStreamWaitEvent(sC, evF, 0);

    // --- stream B: We1 conversion in expert groups (feeds stream C) ---
    const size_t e1slab = (size_t)Dm * 2 * HRt;
    for (int g = 0; g < NGRP; g++) {
        wconv_ilv_k<<<dim3((HRt / 4 + 255) / 256, Dm, EPG), 256, 0, sB>>>(
            We1 + (size_t)g * EPG * e1slab,
            p_e1 + (size_t)g * EPG * e1slab, Dm, HRt);
        cudaEventRecord(evG[g], sB);
    }

    // --- stream C: routing, then routed GEMM1 per group (pipelined vs conv) ---
    router_k<<<NTOK, 128, 0, sC>>>(x, Wr, br);
    prefix_k<<<1, 1, 0, sC>>>();
    for (int g = 0; g < NGRP; g++) {
        cudaStreamWaitEvent(sC, evG[g], 0);
        fgemm<1, true><<<dim3(2 * HRt / 64, NTOK / 128, EPG), 256, GSMEM, sC>>>(
            p_xh, p_xl, p_e1, be1, nullptr, p_arh, p_arl,
            0, 2 * HRt, Dm, g * EPG);
    }
    cudaEventRecord(evJ, sC);

    // --- origin stream (branch A): shared expert path + We2 conversion ---
    wconv_ilv_k<<<dim3((HSh / 4 + 255) / 256, Dm, 1), 256>>>(
        Ws1, p_w1, Dm, HSh);
    fgemm<0, true><<<dim3(2 * HSh / 64, NTOK / 128), 256, GSMEM>>>(
        p_xh, p_xl, p_w1, bs1, nullptr, p_ash, p_asl, NTOK, 2 * HSh, Dm, 0);
    conv1_k<<<(HSh * Dm / 4 + 255) / 256, 256>>>(
        (const float4*)Ws2, (uint2*)p_w2, HSh * Dm / 4);
    fgemm<0, false><<<dim3(Dm / 64, NTOK / 128), 256, GSMEM>>>(
        p_ash, p_asl, p_w2, bs2, out, nullptr, nullptr, NTOK, Dm, HSh, 0);
    conv1_k<<<(NEXP * HRt * Dm / 4 + 255) / 256, 256>>>(
        (const float4*)We2, (uint2*)p_e2, NEXP * HRt * Dm / 4);

    // --- join: routed GEMM2 needs out + We2 (origin) and g_ar (stream C) ---
    cudaStreamWaitEvent(0, evJ, 0);
    fgemm<2, false><<<dim3(Dm / 64, NTOK / 128, NEXP), 256, GSMEM>>>(
        p_arh, p_arl, p_e2, be2, out, nullptr, nullptr, 0, Dm, HRt, 0);
}